// round 11
// baseline (speedup 1.0000x reference)
#include <cuda_runtime.h>
#include <cuda_bf16.h>
#include <cstdint>

#define B_ 16
#define C_ 16
#define P_ 512
#define D_ 256

// ---- scratch (__device__ globals) ----
__device__ unsigned g_Qb[(size_t)B_ * C_ * P_ * 128];   // bf16 query pairs [bc][p][kpair]
__device__ unsigned g_Cx[(size_t)B_ * C_ * P_ * 128];   // bf16 ctx pairs   [bc][p][kpair]
__device__ unsigned g_Wb[(size_t)3 * C_ * D_ * 128];    // bf16 W pairs [which][c][n][kpair]
__device__ unsigned g_Qu[(size_t)B_ * C_ * P_ * 128];   // Q proj out [p][kpair]
__device__ unsigned g_Ku[(size_t)B_ * C_ * P_ * 128];   // K proj out [p][kpair]
__device__ __nv_bfloat16 g_Vt[(size_t)B_ * C_ * D_ * P_]; // V proj out, transposed [d][p]

__device__ __forceinline__ unsigned pk(float lo, float hi) {
    unsigned r;
    asm("cvt.rn.bf16x2.f32 %0, %1, %2;" : "=r"(r) : "f"(hi), "f"(lo));
    return r;
}
__device__ __forceinline__ void mma16(float* c, const unsigned* a, const unsigned* b) {
    asm volatile(
        "mma.sync.aligned.m16n8k16.row.col.f32.bf16.bf16.f32 "
        "{%0,%1,%2,%3}, {%4,%5,%6,%7}, {%8,%9}, {%0,%1,%2,%3};"
        : "+f"(c[0]), "+f"(c[1]), "+f"(c[2]), "+f"(c[3])
        : "r"(a[0]), "r"(a[1]), "r"(a[2]), "r"(a[3]), "r"(b[0]), "r"(b[1]));
}
__device__ __forceinline__ void ldsm4(unsigned& r0, unsigned& r1, unsigned& r2, unsigned& r3, unsigned addr) {
    asm volatile("ldmatrix.sync.aligned.m8n8.x4.shared.b16 {%0,%1,%2,%3}, [%4];"
        : "=r"(r0), "=r"(r1), "=r"(r2), "=r"(r3) : "r"(addr));
}
__device__ __forceinline__ void cpa16(void* s, const void* g) {
    unsigned sa = (unsigned)__cvta_generic_to_shared(s);
    asm volatile("cp.async.ca.shared.global [%0], [%1], 16;" :: "r"(sa), "l"(g));
}
#define CP_COMMIT() asm volatile("cp.async.commit_group;")
#define CP_WAIT0()  asm volatile("cp.async.wait_group 0;")
#define CP_WAIT1()  asm volatile("cp.async.wait_group 1;")

// ============================================================
// Kernel A: prep — bf16 query copy + bf16 ctx (= S - aw*q)
// ============================================================
__global__ __launch_bounds__(256) void k_prep(const float* __restrict__ query,
                                              const float* __restrict__ aw) {
    int idx = blockIdx.x * 256 + threadIdx.x;
    int d4 = idx & 63;
    int p  = (idx >> 6) & 511;
    int b  = idx >> 15;

    float4 qv[16];
    float4 S = make_float4(0.f, 0.f, 0.f, 0.f);
#pragma unroll
    for (int c = 0; c < 16; c++) {
        qv[c] = *(const float4*)(query + ((size_t)((b * 16 + c) * 512 + p) * 64 + d4) * 4);
        float4 a = *(const float4*)(aw + ((size_t)(c * 512 + p) * 64 + d4) * 4);
        S.x += a.x * qv[c].x; S.y += a.y * qv[c].y;
        S.z += a.z * qv[c].z; S.w += a.w * qv[c].w;
        uint2 u; u.x = pk(qv[c].x, qv[c].y); u.y = pk(qv[c].z, qv[c].w);
        *(uint2*)&g_Qb[(size_t)((b * 16 + c) * 512 + p) * 128 + d4 * 2] = u;
    }
#pragma unroll
    for (int c = 0; c < 16; c++) {
        float4 a = *(const float4*)(aw + ((size_t)(c * 512 + p) * 64 + d4) * 4);
        float4 cx;
        cx.x = fmaf(-a.x, qv[c].x, S.x);
        cx.y = fmaf(-a.y, qv[c].y, S.y);
        cx.z = fmaf(-a.z, qv[c].z, S.z);
        cx.w = fmaf(-a.w, qv[c].w, S.w);
        uint2 u; u.x = pk(cx.x, cx.y); u.y = pk(cx.z, cx.w);
        *(uint2*)&g_Cx[(size_t)((b * 16 + c) * 512 + p) * 128 + d4 * 2] = u;
    }
}

// ============================================================
// Kernel B: weight convert+transpose -> g_Wb[which][c][n][kpair]
// ============================================================
__global__ __launch_bounds__(256) void k_wconv(const float* __restrict__ wq,
                                               const float* __restrict__ wk,
                                               const float* __restrict__ wv) {
    __shared__ unsigned sm[32][33];
    int t = blockIdx.x;
    int nb = t & 7, kb = (t >> 3) & 3, c = (t >> 5) & 15, w = t >> 9;
    const float* W = ((w == 0) ? wq : (w == 1) ? wk : wv) + c * D_ * D_;
    int tid = threadIdx.x;
    int coln = tid & 31, rowk = tid >> 5;
#pragma unroll
    for (int i = 0; i < 4; i++) {
        int kk = kb * 32 + rowk + i * 8;
        int n = nb * 32 + coln;
        sm[rowk + i * 8][coln] = pk(W[(2 * kk) * D_ + n], W[(2 * kk + 1) * D_ + n]);
    }
    __syncthreads();
    unsigned* outb = g_Wb + (size_t)(w * 16 + c) * D_ * 128;
    int kkc = tid & 31, rn = tid >> 5;
#pragma unroll
    for (int i = 0; i < 4; i++) {
        int n = nb * 32 + rn + i * 8;
        outb[n * 128 + kb * 32 + kkc] = sm[kkc][rn + i * 8];
    }
}

// ============================================================
// Kernel C: projections — R10 version (reg-capped, 2 CTAs/SM).
// ============================================================
__global__ __launch_bounds__(256, 2) void k_proj(
    const float* __restrict__ bq, const float* __restrict__ bk, const float* __restrict__ bv)
{
    int z = blockIdx.z;
    int which = z % 3;
    int bc = z / 3;
    int c = bc & 15;

    const float* bias = ((which == 0) ? bq : (which == 1) ? bk : bv) + c * D_;
    const unsigned* Asrc = ((which == 0) ? g_Qb : g_Cx) + (size_t)bc * P_ * 128;
    const unsigned* Bsrc = g_Wb + (size_t)(which * 16 + c) * D_ * 128;

    int m0 = blockIdx.x * 128;
    int n0 = blockIdx.y * 128;

    __shared__ unsigned As[2][128 * 20];
    __shared__ unsigned Bs[2][128 * 20];

    int tid = threadIdx.x;
    int wid = tid >> 5, lane = tid & 31;
    int wm = wid & 1, wn = wid >> 1;
    int g = lane >> 2, tq = lane & 3;

    unsigned a_lane = (unsigned)((wm * 64 + (lane & 7) + ((lane >> 3) & 1) * 8) * 20 + ((lane >> 4) & 1) * 4);
    unsigned b_lane = (unsigned)((wn * 32 + (lane & 7) + ((lane >> 4) & 1) * 8) * 20 + ((lane >> 3) & 1) * 4);

    float acc[4][4][4];
#pragma unroll
    for (int i = 0; i < 4; i++)
#pragma unroll
        for (int j = 0; j < 4; j++)
#pragma unroll
            for (int e = 0; e < 4; e++) acc[i][j][e] = 0.f;

#pragma unroll
    for (int i = 0; i < 2; i++) {
        int idx = tid + i * 256;
        int r = idx >> 2, c4 = (idx & 3) * 4;
        cpa16(&As[0][r * 20 + c4], Asrc + (m0 + r) * 128 + c4);
        cpa16(&Bs[0][r * 20 + c4], Bsrc + (n0 + r) * 128 + c4);
    }
    CP_COMMIT();

    for (int t = 0; t < 8; t++) {
        int cur = t & 1, nxt = cur ^ 1;
        if (t < 7) {
            int kp = (t + 1) * 16;
#pragma unroll
            for (int i = 0; i < 2; i++) {
                int idx = tid + i * 256;
                int r = idx >> 2, c4 = (idx & 3) * 4;
                cpa16(&As[nxt][r * 20 + c4], Asrc + (m0 + r) * 128 + kp + c4);
                cpa16(&Bs[nxt][r * 20 + c4], Bsrc + (n0 + r) * 128 + kp + c4);
            }
            CP_COMMIT();
            CP_WAIT1();
        } else {
            CP_WAIT0();
        }
        __syncthreads();

        unsigned as_addr = (unsigned)__cvta_generic_to_shared(&As[cur][0]) + a_lane * 4;
        unsigned bs_addr = (unsigned)__cvta_generic_to_shared(&Bs[cur][0]) + b_lane * 4;
#pragma unroll
        for (int kg = 0; kg < 2; kg++) {
            unsigned a[4][4];
#pragma unroll
            for (int mt = 0; mt < 4; mt++)
                ldsm4(a[mt][0], a[mt][1], a[mt][2], a[mt][3],
                      as_addr + (mt * 16 * 20 + kg * 8) * 4);
#pragma unroll
            for (int ntp = 0; ntp < 2; ntp++) {
                unsigned b0, b1, b2, b3;
                ldsm4(b0, b1, b2, b3, bs_addr + (ntp * 16 * 20 + kg * 8) * 4);
                unsigned bl[2] = { b0, b1 }, bh[2] = { b2, b3 };
#pragma unroll
                for (int mt = 0; mt < 4; mt++) {
                    mma16(acc[mt][2 * ntp], a[mt], bl);
                    mma16(acc[mt][2 * ntp + 1], a[mt], bh);
                }
            }
        }
        __syncthreads();
    }

    if (which == 2) {
        __nv_bfloat16* vt = g_Vt + (size_t)bc * D_ * P_;
#pragma unroll
        for (int mt = 0; mt < 4; mt++) {
#pragma unroll
            for (int nt = 0; nt < 4; nt++) {
                int row = m0 + wm * 64 + mt * 16 + g;
                int col = n0 + wn * 32 + nt * 8 + tq * 2;
                float b0v = bias[col], b1v = bias[col + 1];
                vt[col * P_ + row]           = __float2bfloat16(fmaxf(acc[mt][nt][0] + b0v, 0.f));
                vt[(col + 1) * P_ + row]     = __float2bfloat16(fmaxf(acc[mt][nt][1] + b1v, 0.f));
                vt[col * P_ + row + 8]       = __float2bfloat16(fmaxf(acc[mt][nt][2] + b0v, 0.f));
                vt[(col + 1) * P_ + row + 8] = __float2bfloat16(fmaxf(acc[mt][nt][3] + b1v, 0.f));
            }
        }
    } else {
        unsigned* outu = ((which == 0) ? g_Qu : g_Ku) + (size_t)bc * P_ * 128;
        float scale = (which == 0) ? 0.0625f : 1.f;
#pragma unroll
        for (int mt = 0; mt < 4; mt++) {
#pragma unroll
            for (int nt = 0; nt < 4; nt++) {
                int row = m0 + wm * 64 + mt * 16 + g;
                int col = n0 + wn * 32 + nt * 8 + tq * 2;
                float b0v = bias[col], b1v = bias[col + 1];
                outu[row * 128 + (col >> 1)] =
                    pk(fmaxf(acc[mt][nt][0] + b0v, 0.f) * scale,
                       fmaxf(acc[mt][nt][1] + b1v, 0.f) * scale);
                outu[(row + 8) * 128 + (col >> 1)] =
                    pk(fmaxf(acc[mt][nt][2] + b0v, 0.f) * scale,
                       fmaxf(acc[mt][nt][3] + b1v, 0.f) * scale);
            }
        }
    }
}

// ============================================================
// Kernel D v4: flash attention — 512 threads (16 warps, 4/SMSP).
// Warp w: q-rows (w>>1)*16..+15, column half h=w&1.
// S: warp computes 16x32 of scores; O: warp computes 16x128 of output.
// P exchanged between half-pair warps via smem (18KB).
// ============================================================
#define OFF_Q  0
#define OFF_K0 (128 * 132)
#define OFF_K1 (OFF_K0 + 64 * 132)
#define OFF_V0 (OFF_K1 + 64 * 132)
#define OFF_V1 (OFF_V0 + 256 * 36)
#define OFF_P  (OFF_V1 + 256 * 36)
#define FA_SMEM ((OFF_P + 128 * 36) * 4)    // 227,328 B

extern __shared__ unsigned sm_u[];

__device__ __forceinline__ void stage_k4(unsigned* dst, const unsigned* Ksrc, int kv0, int tid) {
#pragma unroll
    for (int i = 0; i < 4; i++) {
        int idx = i * 512 + tid;            // 0..2047
        int r = idx >> 5, cu = (idx & 31) * 4;
        cpa16(&dst[r * 132 + cu], Ksrc + (kv0 + r) * 128 + cu);
    }
}
__device__ __forceinline__ void stage_v4(unsigned* dst, const unsigned* Vsrc, int kv0, int tid) {
#pragma unroll
    for (int i = 0; i < 4; i++) {
        int idx = i * 512 + tid;            // 0..2047
        int d = idx >> 3, cu = (idx & 7) * 4;
        cpa16(&dst[d * 36 + cu], Vsrc + d * 256 + (kv0 >> 1) + cu);
    }
}

__global__ __launch_bounds__(512, 1) void k_attn(float* __restrict__ outp) {
    int bc = blockIdx.y;
    int q0 = blockIdx.x * 128;
    const unsigned* Qsrc = g_Qu + (size_t)bc * P_ * 128;
    const unsigned* Ksrc = g_Ku + (size_t)bc * P_ * 128;
    const unsigned* Vsrc = (const unsigned*)(g_Vt + (size_t)bc * D_ * P_);
    float* O = outp + (size_t)bc * P_ * D_;

    unsigned* Kb[2] = { sm_u + OFF_K0, sm_u + OFF_K1 };
    unsigned* Vb[2] = { sm_u + OFF_V0, sm_u + OFF_V1 };

    int tid = threadIdx.x;
    int wid = tid >> 5, lane = tid & 31;
    int g = lane >> 2, tq = lane & 3;
    int rg = wid >> 1;                      // row-group 0..7
    int h  = wid & 1;                       // column half
    int mr0 = rg * 16;

    unsigned q_lane = (unsigned)((mr0 + (lane & 7) + ((lane >> 3) & 1) * 8) * 132 + ((lane >> 4) & 1) * 4);
    unsigned k_lane = (unsigned)(((lane & 7) + ((lane >> 4) & 1) * 8) * 132 + ((lane >> 3) & 1) * 4);
    unsigned v_lane = (unsigned)(((lane & 7) + ((lane >> 4) & 1) * 8) * 36 + ((lane >> 3) & 1) * 4);
    unsigned p_lane = (unsigned)((mr0 + (lane & 7) + ((lane >> 3) & 1) * 8) * 36 + ((lane >> 4) & 1) * 4);

    // ---- preload Q (128x256) + tile 0 ----
#pragma unroll
    for (int i = 0; i < 8; i++) {
        int idx = i * 512 + tid;            // 0..4095
        int r = idx >> 5, cu = (idx & 31) * 4;
        cpa16(&sm_u[OFF_Q + r * 132 + cu], Qsrc + (q0 + r) * 128 + cu);
    }
    stage_k4(Kb[0], Ksrc, 0, tid);
    stage_v4(Vb[0], Vsrc, 0, tid);
    CP_COMMIT();

    float l0 = 0.f, l1 = 0.f;
    float Oa[16][4];
#pragma unroll
    for (int nt = 0; nt < 16; nt++)
#pragma unroll
        for (int e = 0; e < 4; e++) Oa[nt][e] = 0.f;

    CP_WAIT0();
    __syncthreads();

    unsigned qs_addr = (unsigned)__cvta_generic_to_shared(sm_u + OFF_Q) + q_lane * 4;
    unsigned ps_base = (unsigned)__cvta_generic_to_shared(sm_u + OFF_P) + p_lane * 4;

    for (int t = 0; t < 8; t++) {
        int cur = t & 1, nxt = cur ^ 1;
        if (t < 7) {
            stage_k4(Kb[nxt], Ksrc, (t + 1) * 64, tid);
            stage_v4(Vb[nxt], Vsrc, (t + 1) * 64, tid);
            CP_COMMIT();
        }
        unsigned ks_addr = (unsigned)__cvta_generic_to_shared(Kb[cur]) + k_lane * 4;
        unsigned vs_addr = (unsigned)__cvta_generic_to_shared(Vb[cur]) + v_lane * 4;

        // ---- S = Q(16 rows) @ K^T (warp's 32 kv cols) ----
        float sacc[4][4];
#pragma unroll
        for (int nt = 0; nt < 4; nt++)
#pragma unroll
            for (int e = 0; e < 4; e++) sacc[nt][e] = 0.f;

#pragma unroll
        for (int kg = 0; kg < 16; kg++) {
            unsigned a[4];
            ldsm4(a[0], a[1], a[2], a[3], qs_addr + kg * 32);
#pragma unroll
            for (int ntp = 0; ntp < 2; ntp++) {
                unsigned b0, b1, b2, b3;
                ldsm4(b0, b1, b2, b3, ks_addr + ((h * 2 + ntp) * 16 * 132 + kg * 8) * 4);
                unsigned bl[2] = { b0, b1 }, bh[2] = { b2, b3 };
                mma16(sacc[2 * ntp], a, bl);
                mma16(sacc[2 * ntp + 1], a, bh);
            }
        }

        // ---- exp (shift-invariant softmax; scores bounded) ----
#pragma unroll
        for (int nt = 0; nt < 4; nt++) {
            sacc[nt][0] = __expf(sacc[nt][0]);
            sacc[nt][1] = __expf(sacc[nt][1]);
            sacc[nt][2] = __expf(sacc[nt][2]);
            sacc[nt][3] = __expf(sacc[nt][3]);
            l0 += sacc[nt][0] + sacc[nt][1];
            l1 += sacc[nt][2] + sacc[nt][3];
        }

        // ---- write own P half to smem (conflict-free) ----
        {
            unsigned* Pp = sm_u + OFF_P;
            int r0 = (mr0 + g) * 36 + h * 16 + tq;
            int r1 = (mr0 + g + 8) * 36 + h * 16 + tq;
#pragma unroll
            for (int nt = 0; nt < 4; nt++) {
                Pp[r0 + nt * 4] = pk(sacc[nt][0], sacc[nt][1]);
                Pp[r1 + nt * 4] = pk(sacc[nt][2], sacc[nt][3]);
            }
        }
        __syncthreads();

        // ---- O += P(16x64) @ V (warp's 128 d cols) ----
#pragma unroll
        for (int kg = 0; kg < 4; kg++) {
            unsigned a[4];
            if ((kg >> 1) == h) {
                int nt0 = (kg & 1) * 2;
                a[0] = pk(sacc[nt0][0], sacc[nt0][1]);
                a[1] = pk(sacc[nt0][2], sacc[nt0][3]);
                a[2] = pk(sacc[nt0 + 1][0], sacc[nt0 + 1][1]);
                a[3] = pk(sacc[nt0 + 1][2], sacc[nt0 + 1][3]);
            } else {
                ldsm4(a[0], a[1], a[2], a[3], ps_base + kg * 32);
            }
#pragma unroll
            for (int ntp = 0; ntp < 8; ntp++) {
                unsigned b0, b1, b2, b3;
                ldsm4(b0, b1, b2, b3, vs_addr + ((h * 8 + ntp) * 16 * 36 + kg * 8) * 4);
                unsigned bl[2] = { b0, b1 }, bh[2] = { b2, b3 };
                mma16(Oa[2 * ntp], a, bl);
                mma16(Oa[2 * ntp + 1], a, bh);
            }
        }

        CP_WAIT0();
        __syncthreads();
    }

    // ---- epilogue: l merge across column-half warp pair ----
#pragma unroll
    for (int o = 1; o <= 2; o <<= 1) {
        l0 += __shfl_xor_sync(0xFFFFFFFFu, l0, o);
        l1 += __shfl_xor_sync(0xFFFFFFFFu, l1, o);
    }
    float* lf = (float*)(sm_u + OFF_P);     // P buffer is free now
    if (tq == 0) {
        lf[h * 128 + mr0 + g] = l0;
        lf[h * 128 + mr0 + g + 8] = l1;
    }
    __syncthreads();
    float inv0 = 1.f / (lf[mr0 + g] + lf[128 + mr0 + g]);
    float inv1 = 1.f / (lf[mr0 + g + 8] + lf[128 + mr0 + g + 8]);

    int row0 = q0 + mr0 + g;
#pragma unroll
    for (int nt = 0; nt < 16; nt++) {
        int col = h * 128 + nt * 8 + tq * 2;
        *(float2*)&O[row0 * D_ + col] = make_float2(Oa[nt][0] * inv0, Oa[nt][1] * inv0);
        *(float2*)&O[(row0 + 8) * D_ + col] = make_float2(Oa[nt][2] * inv1, Oa[nt][3] * inv1);
    }
}

// ============================================================
extern "C" void kernel_launch(void* const* d_in, const int* in_sizes, int n_in,
                              void* d_out, int out_size) {
    const float* query = (const float*)d_in[0];
    const float* aw    = (const float*)d_in[1];
    const float* wq    = (const float*)d_in[2];
    const float* wk    = (const float*)d_in[3];
    const float* wv    = (const float*)d_in[4];
    const float* bq    = (const float*)d_in[5];
    const float* bk    = (const float*)d_in[6];
    const float* bv    = (const float*)d_in[7];
    float* out = (float*)d_out;

    cudaFuncSetAttribute(k_attn, cudaFuncAttributeMaxDynamicSharedMemorySize, FA_SMEM);

    k_prep<<<(B_ * P_ * D_ / 4) / 256, 256>>>(query, aw);
    k_wconv<<<3 * 16 * 4 * 8, 256>>>(wq, wk, wv);

    dim3 gp(P_ / 128, D_ / 128, B_ * C_ * 3);
    k_proj<<<gp, 256>>>(bq, bk, bv);

    dim3 ga(P_ / 128, B_ * C_);
    k_attn<<<ga, 512, FA_SMEM>>>(out);
}

// round 13
// speedup vs baseline: 1.0504x; 1.0504x over previous
#include <cuda_runtime.h>
#include <cuda_bf16.h>
#include <cstdint>

#define B_ 16
#define C_ 16
#define P_ 512
#define D_ 256

// ---- scratch (__device__ globals) ----
__device__ unsigned g_Qb[(size_t)B_ * C_ * P_ * 128];   // bf16 query pairs [bc][p][kpair]
__device__ unsigned g_Cx[(size_t)B_ * C_ * P_ * 128];   // bf16 ctx pairs   [bc][p][kpair]
__device__ unsigned g_Wb[(size_t)3 * C_ * D_ * 128];    // bf16 W pairs [which][c][n][kpair]
__device__ unsigned g_Qu[(size_t)B_ * C_ * P_ * 128];   // Q proj out [p][kpair]
__device__ unsigned g_Ku[(size_t)B_ * C_ * P_ * 128];   // K proj out [p][kpair]
__device__ __nv_bfloat16 g_Vt[(size_t)B_ * C_ * D_ * P_]; // V proj out, transposed [d][p]

__device__ __forceinline__ unsigned pk(float lo, float hi) {
    unsigned r;
    asm("cvt.rn.bf16x2.f32 %0, %1, %2;" : "=r"(r) : "f"(hi), "f"(lo));
    return r;
}
__device__ __forceinline__ void mma16(float* c, const unsigned* a, const unsigned* b) {
    asm volatile(
        "mma.sync.aligned.m16n8k16.row.col.f32.bf16.bf16.f32 "
        "{%0,%1,%2,%3}, {%4,%5,%6,%7}, {%8,%9}, {%0,%1,%2,%3};"
        : "+f"(c[0]), "+f"(c[1]), "+f"(c[2]), "+f"(c[3])
        : "r"(a[0]), "r"(a[1]), "r"(a[2]), "r"(a[3]), "r"(b[0]), "r"(b[1]));
}
__device__ __forceinline__ void ldsm4(unsigned& r0, unsigned& r1, unsigned& r2, unsigned& r3, unsigned addr) {
    asm volatile("ldmatrix.sync.aligned.m8n8.x4.shared.b16 {%0,%1,%2,%3}, [%4];"
        : "=r"(r0), "=r"(r1), "=r"(r2), "=r"(r3) : "r"(addr));
}
__device__ __forceinline__ void cpa16(void* s, const void* g) {
    unsigned sa = (unsigned)__cvta_generic_to_shared(s);
    asm volatile("cp.async.ca.shared.global [%0], [%1], 16;" :: "r"(sa), "l"(g));
}
#define CP_COMMIT() asm volatile("cp.async.commit_group;")
#define CP_WAIT0()  asm volatile("cp.async.wait_group 0;")
#define CP_WAIT1()  asm volatile("cp.async.wait_group 1;")

// ============================================================
// Kernel A: prep — bf16 query copy + bf16 ctx (= S - aw*q)
// ============================================================
__global__ __launch_bounds__(256) void k_prep(const float* __restrict__ query,
                                              const float* __restrict__ aw) {
    int idx = blockIdx.x * 256 + threadIdx.x;
    int d4 = idx & 63;
    int p  = (idx >> 6) & 511;
    int b  = idx >> 15;

    float4 qv[16];
    float4 S = make_float4(0.f, 0.f, 0.f, 0.f);
#pragma unroll
    for (int c = 0; c < 16; c++) {
        qv[c] = *(const float4*)(query + ((size_t)((b * 16 + c) * 512 + p) * 64 + d4) * 4);
        float4 a = *(const float4*)(aw + ((size_t)(c * 512 + p) * 64 + d4) * 4);
        S.x += a.x * qv[c].x; S.y += a.y * qv[c].y;
        S.z += a.z * qv[c].z; S.w += a.w * qv[c].w;
        uint2 u; u.x = pk(qv[c].x, qv[c].y); u.y = pk(qv[c].z, qv[c].w);
        *(uint2*)&g_Qb[(size_t)((b * 16 + c) * 512 + p) * 128 + d4 * 2] = u;
    }
#pragma unroll
    for (int c = 0; c < 16; c++) {
        float4 a = *(const float4*)(aw + ((size_t)(c * 512 + p) * 64 + d4) * 4);
        float4 cx;
        cx.x = fmaf(-a.x, qv[c].x, S.x);
        cx.y = fmaf(-a.y, qv[c].y, S.y);
        cx.z = fmaf(-a.z, qv[c].z, S.z);
        cx.w = fmaf(-a.w, qv[c].w, S.w);
        uint2 u; u.x = pk(cx.x, cx.y); u.y = pk(cx.z, cx.w);
        *(uint2*)&g_Cx[(size_t)((b * 16 + c) * 512 + p) * 128 + d4 * 2] = u;
    }
}

// ============================================================
// Kernel B: weight convert+transpose -> g_Wb[which][c][n][kpair]
// ============================================================
__global__ __launch_bounds__(256) void k_wconv(const float* __restrict__ wq,
                                               const float* __restrict__ wk,
                                               const float* __restrict__ wv) {
    __shared__ unsigned sm[32][33];
    int t = blockIdx.x;
    int nb = t & 7, kb = (t >> 3) & 3, c = (t >> 5) & 15, w = t >> 9;
    const float* W = ((w == 0) ? wq : (w == 1) ? wk : wv) + c * D_ * D_;
    int tid = threadIdx.x;
    int coln = tid & 31, rowk = tid >> 5;
#pragma unroll
    for (int i = 0; i < 4; i++) {
        int kk = kb * 32 + rowk + i * 8;
        int n = nb * 32 + coln;
        sm[rowk + i * 8][coln] = pk(W[(2 * kk) * D_ + n], W[(2 * kk + 1) * D_ + n]);
    }
    __syncthreads();
    unsigned* outb = g_Wb + (size_t)(w * 16 + c) * D_ * 128;
    int kkc = tid & 31, rn = tid >> 5;
#pragma unroll
    for (int i = 0; i < 4; i++) {
        int n = nb * 32 + rn + i * 8;
        outb[n * 128 + kb * 32 + kkc] = sm[kkc][rn + i * 8];
    }
}

// ============================================================
// Kernel C: projections v4 — BM=128 BN=128 BK=32 (measured-best tile),
// 3-stage cp.async pipeline, ONE __syncthreads per k-iter,
// reg-capped for 2 CTAs/SM. Dynamic smem 60KB.
// ============================================================
#define PJ3_AS  2560                 // 128*20 words
#define PJ3_STG (2 * PJ3_AS)         // As + Bs per stage
#define PJ3_SMEM (3 * PJ3_STG * 4)   // 61440 B

extern __shared__ unsigned sm_u[];

__global__ __launch_bounds__(256, 2) void k_proj(
    const float* __restrict__ bq, const float* __restrict__ bk, const float* __restrict__ bv)
{
    int z = blockIdx.z;
    int which = z % 3;
    int bc = z / 3;
    int c = bc & 15;

    const float* bias = ((which == 0) ? bq : (which == 1) ? bk : bv) + c * D_;
    const unsigned* Asrc = ((which == 0) ? g_Qb : g_Cx) + (size_t)bc * P_ * 128;
    const unsigned* Bsrc = g_Wb + (size_t)(which * 16 + c) * D_ * 128;

    int m0 = blockIdx.x * 128;
    int n0 = blockIdx.y * 128;

    int tid = threadIdx.x;
    int wid = tid >> 5, lane = tid & 31;
    int wm = wid & 1, wn = wid >> 1;
    int g = lane >> 2, tq = lane & 3;

    unsigned a_lane = (unsigned)((wm * 64 + (lane & 7) + ((lane >> 3) & 1) * 8) * 20 + ((lane >> 4) & 1) * 4);
    unsigned b_lane = (unsigned)((wn * 32 + (lane & 7) + ((lane >> 4) & 1) * 8) * 20 + ((lane >> 3) & 1) * 4);

    float acc[4][4][4];
#pragma unroll
    for (int i = 0; i < 4; i++)
#pragma unroll
        for (int j = 0; j < 4; j++)
#pragma unroll
            for (int e = 0; e < 4; e++) acc[i][j][e] = 0.f;

    // stage s covers kpairs [s*16, s*16+16); buffer s%3
    auto stage = [&](int s) {
        unsigned* As = sm_u + (s % 3) * PJ3_STG;
        unsigned* Bs = As + PJ3_AS;
        int kp = s * 16;
#pragma unroll
        for (int i = 0; i < 2; i++) {
            int idx = tid + i * 256;
            int r = idx >> 2, c4 = (idx & 3) * 4;
            cpa16(&As[r * 20 + c4], Asrc + (m0 + r) * 128 + kp + c4);
            cpa16(&Bs[r * 20 + c4], Bsrc + (n0 + r) * 128 + kp + c4);
        }
        CP_COMMIT();
    };

    stage(0);
    stage(1);

    for (int t = 0; t < 8; t++) {
        if (t < 7) { CP_WAIT1(); } else { CP_WAIT0(); }
        __syncthreads();
        if (t < 6) stage(t + 2);

        unsigned* As = sm_u + (t % 3) * PJ3_STG;
        unsigned as_addr = (unsigned)__cvta_generic_to_shared(As) + a_lane * 4;
        unsigned bs_addr = (unsigned)__cvta_generic_to_shared(As + PJ3_AS) + b_lane * 4;
#pragma unroll
        for (int kg = 0; kg < 2; kg++) {
            unsigned a[4][4];
#pragma unroll
            for (int mt = 0; mt < 4; mt++)
                ldsm4(a[mt][0], a[mt][1], a[mt][2], a[mt][3],
                      as_addr + (mt * 16 * 20 + kg * 8) * 4);
#pragma unroll
            for (int ntp = 0; ntp < 2; ntp++) {
                unsigned b0, b1, b2, b3;
                ldsm4(b0, b1, b2, b3, bs_addr + (ntp * 16 * 20 + kg * 8) * 4);
                unsigned bl[2] = { b0, b1 }, bh[2] = { b2, b3 };
#pragma unroll
                for (int mt = 0; mt < 4; mt++) {
                    mma16(acc[mt][2 * ntp], a[mt], bl);
                    mma16(acc[mt][2 * ntp + 1], a[mt], bh);
                }
            }
        }
    }

    if (which == 2) {
        __nv_bfloat16* vt = g_Vt + (size_t)bc * D_ * P_;
#pragma unroll
        for (int mt = 0; mt < 4; mt++) {
#pragma unroll
            for (int nt = 0; nt < 4; nt++) {
                int row = m0 + wm * 64 + mt * 16 + g;
                int col = n0 + wn * 32 + nt * 8 + tq * 2;
                float b0v = bias[col], b1v = bias[col + 1];
                vt[col * P_ + row]           = __float2bfloat16(fmaxf(acc[mt][nt][0] + b0v, 0.f));
                vt[(col + 1) * P_ + row]     = __float2bfloat16(fmaxf(acc[mt][nt][1] + b1v, 0.f));
                vt[col * P_ + row + 8]       = __float2bfloat16(fmaxf(acc[mt][nt][2] + b0v, 0.f));
                vt[(col + 1) * P_ + row + 8] = __float2bfloat16(fmaxf(acc[mt][nt][3] + b1v, 0.f));
            }
        }
    } else {
        unsigned* outu = ((which == 0) ? g_Qu : g_Ku) + (size_t)bc * P_ * 128;
        float scale = (which == 0) ? 0.0625f : 1.f;
#pragma unroll
        for (int mt = 0; mt < 4; mt++) {
#pragma unroll
            for (int nt = 0; nt < 4; nt++) {
                int row = m0 + wm * 64 + mt * 16 + g;
                int col = n0 + wn * 32 + nt * 8 + tq * 2;
                float b0v = bias[col], b1v = bias[col + 1];
                outu[row * 128 + (col >> 1)] =
                    pk(fmaxf(acc[mt][nt][0] + b0v, 0.f) * scale,
                       fmaxf(acc[mt][nt][1] + b1v, 0.f) * scale);
                outu[(row + 8) * 128 + (col >> 1)] =
                    pk(fmaxf(acc[mt][nt][2] + b0v, 0.f) * scale,
                       fmaxf(acc[mt][nt][3] + b1v, 0.f) * scale);
            }
        }
    }
}

// ============================================================
// Kernel D: fused flash attention (R6 known-good, 271.5us).
// exp applied directly (scores bounded), l deferred to epilogue.
// bf16, ldmatrix, double-buffered K/V via cp.async.
// ============================================================
#define QSU (128 * 132)
#define KSU (64 * 132)
#define VSU (256 * 36)
#define OFF_K0 QSU
#define OFF_K1 (QSU + KSU)
#define OFF_V0 (QSU + 2 * KSU)
#define OFF_V1 (QSU + 2 * KSU + VSU)
#define FA_SMEM ((QSU + 2 * KSU + 2 * VSU) * 4)

__device__ __forceinline__ void stage_k(unsigned* dst, const unsigned* Ksrc, int kv0, int tid) {
#pragma unroll
    for (int i = 0; i < 8; i++) {
        int idx = i * 256 + tid;
        int r = idx >> 5, cu = (idx & 31) * 4;
        cpa16(&dst[r * 132 + cu], Ksrc + (kv0 + r) * 128 + cu);
    }
}
__device__ __forceinline__ void stage_v(unsigned* dst, const unsigned* Vsrc, int kv0, int tid) {
#pragma unroll
    for (int i = 0; i < 8; i++) {
        int idx = i * 256 + tid;
        int d = idx >> 3, cu = (idx & 7) * 4;
        cpa16(&dst[d * 36 + cu], Vsrc + d * 256 + (kv0 >> 1) + cu);
    }
}

__global__ __launch_bounds__(256) void k_attn(float* __restrict__ outp) {
    int bc = blockIdx.y;
    int q0 = blockIdx.x * 128;
    const unsigned* Qsrc = g_Qu + (size_t)bc * P_ * 128;
    const unsigned* Ksrc = g_Ku + (size_t)bc * P_ * 128;
    const unsigned* Vsrc = (const unsigned*)(g_Vt + (size_t)bc * D_ * P_);
    float* O = outp + (size_t)bc * P_ * D_;

    unsigned* Qs = sm_u;
    unsigned* Kb[2] = { sm_u + OFF_K0, sm_u + OFF_K1 };
    unsigned* Vb[2] = { sm_u + OFF_V0, sm_u + OFF_V1 };

    int tid = threadIdx.x;
    int wid = tid >> 5, lane = tid & 31;
    int g = lane >> 2, tq = lane & 3;
    int mr0 = wid * 16;

    unsigned q_lane = (unsigned)((mr0 + (lane & 7) + ((lane >> 3) & 1) * 8) * 132 + ((lane >> 4) & 1) * 4);
    unsigned k_lane = (unsigned)(((lane & 7) + ((lane >> 4) & 1) * 8) * 132 + ((lane >> 3) & 1) * 4);
    unsigned v_lane = (unsigned)(((lane & 7) + ((lane >> 4) & 1) * 8) * 36 + ((lane >> 3) & 1) * 4);

    // preload Q + tile 0
#pragma unroll
    for (int i = 0; i < 16; i++) {
        int idx = i * 256 + tid;
        int r = idx >> 5, cu = (idx & 31) * 4;
        cpa16(&Qs[r * 132 + cu], Qsrc + (q0 + r) * 128 + cu);
    }
    stage_k(Kb[0], Ksrc, 0, tid);
    stage_v(Vb[0], Vsrc, 0, tid);
    CP_COMMIT();

    float l0 = 0.f, l1 = 0.f;
    float Oa[32][4];
#pragma unroll
    for (int nt = 0; nt < 32; nt++)
#pragma unroll
        for (int e = 0; e < 4; e++) Oa[nt][e] = 0.f;

    CP_WAIT0();
    __syncthreads();

    unsigned qs_addr = (unsigned)__cvta_generic_to_shared(Qs) + q_lane * 4;

    for (int t = 0; t < 8; t++) {
        int cur = t & 1, nxt = cur ^ 1;
        if (t < 7) {
            stage_k(Kb[nxt], Ksrc, (t + 1) * 64, tid);
            stage_v(Vb[nxt], Vsrc, (t + 1) * 64, tid);
            CP_COMMIT();
        }
        unsigned ks_addr = (unsigned)__cvta_generic_to_shared(Kb[cur]) + k_lane * 4;
        unsigned vs_addr = (unsigned)__cvta_generic_to_shared(Vb[cur]) + v_lane * 4;

        // ---- S = Q @ K_tile^T ----
        float sacc[8][4];
#pragma unroll
        for (int nt = 0; nt < 8; nt++)
#pragma unroll
            for (int e = 0; e < 4; e++) sacc[nt][e] = 0.f;

#pragma unroll
        for (int kg = 0; kg < 16; kg++) {
            unsigned a[4];
            ldsm4(a[0], a[1], a[2], a[3], qs_addr + kg * 32);
#pragma unroll
            for (int ntp = 0; ntp < 4; ntp++) {
                unsigned b0, b1, b2, b3;
                ldsm4(b0, b1, b2, b3, ks_addr + (ntp * 16 * 132 + kg * 8) * 4);
                unsigned bl[2] = { b0, b1 }, bh[2] = { b2, b3 };
                mma16(sacc[2 * ntp], a, bl);
                mma16(sacc[2 * ntp + 1], a, bh);
            }
        }

        // ---- exp (softmax shift-invariant; scores bounded) ----
#pragma unroll
        for (int nt = 0; nt < 8; nt++) {
            sacc[nt][0] = __expf(sacc[nt][0]);
            sacc[nt][1] = __expf(sacc[nt][1]);
            sacc[nt][2] = __expf(sacc[nt][2]);
            sacc[nt][3] = __expf(sacc[nt][3]);
            l0 += sacc[nt][0] + sacc[nt][1];
            l1 += sacc[nt][2] + sacc[nt][3];
        }

        // ---- O += P @ V_tile ----
#pragma unroll
        for (int kg = 0; kg < 4; kg++) {
            unsigned a[4];
            a[0] = pk(sacc[2 * kg][0], sacc[2 * kg][1]);
            a[1] = pk(sacc[2 * kg][2], sacc[2 * kg][3]);
            a[2] = pk(sacc[2 * kg + 1][0], sacc[2 * kg + 1][1]);
            a[3] = pk(sacc[2 * kg + 1][2], sacc[2 * kg + 1][3]);
#pragma unroll
            for (int ntp = 0; ntp < 16; ntp++) {
                unsigned b0, b1, b2, b3;
                ldsm4(b0, b1, b2, b3, vs_addr + (ntp * 16 * 36 + kg * 8) * 4);
                unsigned bl[2] = { b0, b1 }, bh[2] = { b2, b3 };
                mma16(Oa[2 * ntp], a, bl);
                mma16(Oa[2 * ntp + 1], a, bh);
            }
        }

        CP_WAIT0();
        __syncthreads();
    }

    // ---- epilogue: deferred l reduction (quad lanes share rows) ----
#pragma unroll
    for (int o = 1; o <= 2; o <<= 1) {
        l0 += __shfl_xor_sync(0xFFFFFFFFu, l0, o);
        l1 += __shfl_xor_sync(0xFFFFFFFFu, l1, o);
    }
    float inv0 = 1.f / l0, inv1 = 1.f / l1;
    int row0 = q0 + mr0 + g;
#pragma unroll
    for (int nt = 0; nt < 32; nt++) {
        int col = nt * 8 + tq * 2;
        *(float2*)&O[row0 * D_ + col] = make_float2(Oa[nt][0] * inv0, Oa[nt][1] * inv0);
        *(float2*)&O[(row0 + 8) * D_ + col] = make_float2(Oa[nt][2] * inv1, Oa[nt][3] * inv1);
    }
}

// ============================================================
extern "C" void kernel_launch(void* const* d_in, const int* in_sizes, int n_in,
                              void* d_out, int out_size) {
    const float* query = (const float*)d_in[0];
    const float* aw    = (const float*)d_in[1];
    const float* wq    = (const float*)d_in[2];
    const float* wk    = (const float*)d_in[3];
    const float* wv    = (const float*)d_in[4];
    const float* bq    = (const float*)d_in[5];
    const float* bk    = (const float*)d_in[6];
    const float* bv    = (const float*)d_in[7];
    float* out = (float*)d_out;

    cudaFuncSetAttribute(k_attn, cudaFuncAttributeMaxDynamicSharedMemorySize, FA_SMEM);
    cudaFuncSetAttribute(k_proj, cudaFuncAttributeMaxDynamicSharedMemorySize, PJ3_SMEM);

    k_prep<<<(B_ * P_ * D_ / 4) / 256, 256>>>(query, aw);
    k_wconv<<<3 * 16 * 4 * 8, 256>>>(wq, wk, wv);

    dim3 gp(P_ / 128, D_ / 128, B_ * C_ * 3);
    k_proj<<<gp, 256, PJ3_SMEM>>>(bq, bk, bv);

    dim3 ga(P_ / 128, B_ * C_);
    k_attn<<<ga, 256, FA_SMEM>>>(out);
}

// round 14
// speedup vs baseline: 1.0542x; 1.0036x over previous
#include <cuda_runtime.h>
#include <cuda_bf16.h>
#include <cstdint>

#define B_ 16
#define C_ 16
#define P_ 512
#define D_ 256

// ---- scratch (__device__ globals) ----
__device__ unsigned g_Qb[(size_t)B_ * C_ * P_ * 128];   // bf16 query pairs [bc][p][kpair]
__device__ unsigned g_Cx[(size_t)B_ * C_ * P_ * 128];   // bf16 ctx pairs   [bc][p][kpair]
__device__ unsigned g_Wb[(size_t)3 * C_ * D_ * 128];    // bf16 W pairs [which][c][n][kpair]
__device__ unsigned g_Qu[(size_t)B_ * C_ * P_ * 128];   // Q proj out [p][kpair] (scaled by log2e/16)
__device__ unsigned g_Ku[(size_t)B_ * C_ * P_ * 128];   // K proj out [p][kpair]
__device__ __nv_bfloat16 g_Vt[(size_t)B_ * C_ * D_ * P_]; // V proj out, transposed [d][p]

__device__ __forceinline__ unsigned pk(float lo, float hi) {
    unsigned r;
    asm("cvt.rn.bf16x2.f32 %0, %1, %2;" : "=r"(r) : "f"(hi), "f"(lo));
    return r;
}
__device__ __forceinline__ float ex2(float x) {
    float y;
    asm("ex2.approx.f32 %0, %1;" : "=f"(y) : "f"(x));
    return y;
}
__device__ __forceinline__ void mma16(float* c, const unsigned* a, const unsigned* b) {
    asm volatile(
        "mma.sync.aligned.m16n8k16.row.col.f32.bf16.bf16.f32 "
        "{%0,%1,%2,%3}, {%4,%5,%6,%7}, {%8,%9}, {%0,%1,%2,%3};"
        : "+f"(c[0]), "+f"(c[1]), "+f"(c[2]), "+f"(c[3])
        : "r"(a[0]), "r"(a[1]), "r"(a[2]), "r"(a[3]), "r"(b[0]), "r"(b[1]));
}
__device__ __forceinline__ void ldsm4(unsigned& r0, unsigned& r1, unsigned& r2, unsigned& r3, unsigned addr) {
    asm volatile("ldmatrix.sync.aligned.m8n8.x4.shared.b16 {%0,%1,%2,%3}, [%4];"
        : "=r"(r0), "=r"(r1), "=r"(r2), "=r"(r3) : "r"(addr));
}
__device__ __forceinline__ void cpa16(void* s, const void* g) {
    unsigned sa = (unsigned)__cvta_generic_to_shared(s);
    asm volatile("cp.async.ca.shared.global [%0], [%1], 16;" :: "r"(sa), "l"(g));
}
#define CP_COMMIT() asm volatile("cp.async.commit_group;")
#define CP_WAIT0()  asm volatile("cp.async.wait_group 0;")
#define CP_WAIT1()  asm volatile("cp.async.wait_group 1;")

// ============================================================
// Kernel A: prep — bf16 query copy + bf16 ctx (= S - aw*q)
// ============================================================
__global__ __launch_bounds__(256) void k_prep(const float* __restrict__ query,
                                              const float* __restrict__ aw) {
    int idx = blockIdx.x * 256 + threadIdx.x;
    int d4 = idx & 63;
    int p  = (idx >> 6) & 511;
    int b  = idx >> 15;

    float4 qv[16];
    float4 S = make_float4(0.f, 0.f, 0.f, 0.f);
#pragma unroll
    for (int c = 0; c < 16; c++) {
        qv[c] = *(const float4*)(query + ((size_t)((b * 16 + c) * 512 + p) * 64 + d4) * 4);
        float4 a = *(const float4*)(aw + ((size_t)(c * 512 + p) * 64 + d4) * 4);
        S.x += a.x * qv[c].x; S.y += a.y * qv[c].y;
        S.z += a.z * qv[c].z; S.w += a.w * qv[c].w;
        uint2 u; u.x = pk(qv[c].x, qv[c].y); u.y = pk(qv[c].z, qv[c].w);
        *(uint2*)&g_Qb[(size_t)((b * 16 + c) * 512 + p) * 128 + d4 * 2] = u;
    }
#pragma unroll
    for (int c = 0; c < 16; c++) {
        float4 a = *(const float4*)(aw + ((size_t)(c * 512 + p) * 64 + d4) * 4);
        float4 cx;
        cx.x = fmaf(-a.x, qv[c].x, S.x);
        cx.y = fmaf(-a.y, qv[c].y, S.y);
        cx.z = fmaf(-a.z, qv[c].z, S.z);
        cx.w = fmaf(-a.w, qv[c].w, S.w);
        uint2 u; u.x = pk(cx.x, cx.y); u.y = pk(cx.z, cx.w);
        *(uint2*)&g_Cx[(size_t)((b * 16 + c) * 512 + p) * 128 + d4 * 2] = u;
    }
}

// ============================================================
// Kernel B: weight convert+transpose -> g_Wb[which][c][n][kpair]
// ============================================================
__global__ __launch_bounds__(256) void k_wconv(const float* __restrict__ wq,
                                               const float* __restrict__ wk,
                                               const float* __restrict__ wv) {
    __shared__ unsigned sm[32][33];
    int t = blockIdx.x;
    int nb = t & 7, kb = (t >> 3) & 3, c = (t >> 5) & 15, w = t >> 9;
    const float* W = ((w == 0) ? wq : (w == 1) ? wk : wv) + c * D_ * D_;
    int tid = threadIdx.x;
    int coln = tid & 31, rowk = tid >> 5;
#pragma unroll
    for (int i = 0; i < 4; i++) {
        int kk = kb * 32 + rowk + i * 8;
        int n = nb * 32 + coln;
        sm[rowk + i * 8][coln] = pk(W[(2 * kk) * D_ + n], W[(2 * kk + 1) * D_ + n]);
    }
    __syncthreads();
    unsigned* outb = g_Wb + (size_t)(w * 16 + c) * D_ * 128;
    int kkc = tid & 31, rn = tid >> 5;
#pragma unroll
    for (int i = 0; i < 4; i++) {
        int n = nb * 32 + rn + i * 8;
        outb[n * 128 + kb * 32 + kkc] = sm[kkc][rn + i * 8];
    }
}

// ============================================================
// Kernel C: projections v5 — A tile resident (128x256 bf16, staged once),
// persistent over BOTH n-blocks; W streamed through 3-stage pipeline,
// ONE __syncthreads per step. 96KB smem, reg-capped 2 CTAs/SM.
// Halves A-operand DRAM traffic vs v4.
// ============================================================
#define PA_WORDS (128 * 132)          // resident A tile (stride 132)
#define PW_STG   (128 * 20)           // one W stage
#define PJ_SMEM  ((PA_WORDS + 3 * PW_STG) * 4)   // 98,304 B

extern __shared__ unsigned sm_u[];

__global__ __launch_bounds__(256, 2) void k_proj(
    const float* __restrict__ bq, const float* __restrict__ bk, const float* __restrict__ bv)
{
    int z = blockIdx.z;
    int which = z % 3;
    int bc = z / 3;
    int c = bc & 15;

    const float* bias = ((which == 0) ? bq : (which == 1) ? bk : bv) + c * D_;
    const unsigned* Asrc = ((which == 0) ? g_Qb : g_Cx) + (size_t)bc * P_ * 128;
    const unsigned* Bsrc = g_Wb + (size_t)(which * 16 + c) * D_ * 128;

    int m0 = blockIdx.x * 128;

    int tid = threadIdx.x;
    int wid = tid >> 5, lane = tid & 31;
    int wm = wid & 1, wn = wid >> 1;
    int g = lane >> 2, tq = lane & 3;

    unsigned a_lane = (unsigned)((wm * 64 + (lane & 7) + ((lane >> 3) & 1) * 8) * 132 + ((lane >> 4) & 1) * 4);
    unsigned b_lane = (unsigned)((wn * 32 + (lane & 7) + ((lane >> 4) & 1) * 8) * 20 + ((lane >> 3) & 1) * 4);

    unsigned* smA = sm_u;
    unsigned* smW = sm_u + PA_WORDS;

    // ---- stage A tile once (128 rows x 128 words) ----
#pragma unroll
    for (int i = 0; i < 16; i++) {
        int idx = i * 256 + tid;            // 0..4095
        int r = idx >> 5, cu = (idx & 31) * 4;
        cpa16(&smA[r * 132 + cu], Asrc + (m0 + r) * 128 + cu);
    }
    CP_COMMIT();

    // W stage s (s = nb*8 + kt): rows (nb*128 + r), kpairs [kt*16, kt*16+16)
    auto stageW = [&](int s) {
        unsigned* Ws = smW + (s % 3) * PW_STG;
        int nb = s >> 3, kp = (s & 7) * 16;
#pragma unroll
        for (int i = 0; i < 2; i++) {
            int idx = tid + i * 256;        // 0..511
            int r = idx >> 2, c4 = (idx & 3) * 4;
            cpa16(&Ws[r * 20 + c4], Bsrc + (nb * 128 + r) * 128 + kp + c4);
        }
        CP_COMMIT();
    };

    stageW(0);
    stageW(1);

    unsigned as_base = (unsigned)__cvta_generic_to_shared(smA) + a_lane * 4;

    float acc[4][4][4];

    for (int s = 0; s < 16; s++) {
        if ((s & 7) == 0) {
#pragma unroll
            for (int i = 0; i < 4; i++)
#pragma unroll
                for (int j = 0; j < 4; j++)
#pragma unroll
                    for (int e = 0; e < 4; e++) acc[i][j][e] = 0.f;
        }

        if (s < 15) { CP_WAIT1(); } else { CP_WAIT0(); }
        __syncthreads();
        if (s < 14) stageW(s + 2);

        unsigned* Ws = smW + (s % 3) * PW_STG;
        unsigned bs_addr = (unsigned)__cvta_generic_to_shared(Ws) + b_lane * 4;
        unsigned kbase = (unsigned)((s & 7) * 16);
#pragma unroll
        for (int kg = 0; kg < 2; kg++) {
            unsigned a[4][4];
#pragma unroll
            for (int mt = 0; mt < 4; mt++)
                ldsm4(a[mt][0], a[mt][1], a[mt][2], a[mt][3],
                      as_base + (mt * 16 * 132 + kbase + kg * 8) * 4);
#pragma unroll
            for (int ntp = 0; ntp < 2; ntp++) {
                unsigned b0, b1, b2, b3;
                ldsm4(b0, b1, b2, b3, bs_addr + (ntp * 16 * 20 + kg * 8) * 4);
                unsigned bl[2] = { b0, b1 }, bh[2] = { b2, b3 };
#pragma unroll
                for (int mt = 0; mt < 4; mt++) {
                    mma16(acc[mt][2 * ntp], a[mt], bl);
                    mma16(acc[mt][2 * ntp + 1], a[mt], bh);
                }
            }
        }

        // ---- epilogue at end of each n-block ----
        if ((s & 7) == 7) {
            int n0 = (s >> 3) * 128;
            if (which == 2) {
                __nv_bfloat16* vt = g_Vt + (size_t)bc * D_ * P_;
#pragma unroll
                for (int mt = 0; mt < 4; mt++) {
#pragma unroll
                    for (int nt = 0; nt < 4; nt++) {
                        int row = m0 + wm * 64 + mt * 16 + g;
                        int col = n0 + wn * 32 + nt * 8 + tq * 2;
                        float b0v = bias[col], b1v = bias[col + 1];
                        vt[col * P_ + row]           = __float2bfloat16(fmaxf(acc[mt][nt][0] + b0v, 0.f));
                        vt[(col + 1) * P_ + row]     = __float2bfloat16(fmaxf(acc[mt][nt][1] + b1v, 0.f));
                        vt[col * P_ + row + 8]       = __float2bfloat16(fmaxf(acc[mt][nt][2] + b0v, 0.f));
                        vt[(col + 1) * P_ + row + 8] = __float2bfloat16(fmaxf(acc[mt][nt][3] + b1v, 0.f));
                    }
                }
            } else {
                unsigned* outu = ((which == 0) ? g_Qu : g_Ku) + (size_t)bc * P_ * 128;
                // Q scale folds 1/sqrt(D)=1/16 and log2(e) for the attn exp2
                float scale = (which == 0) ? 0.09016994f : 1.f;
#pragma unroll
                for (int mt = 0; mt < 4; mt++) {
#pragma unroll
                    for (int nt = 0; nt < 4; nt++) {
                        int row = m0 + wm * 64 + mt * 16 + g;
                        int col = n0 + wn * 32 + nt * 8 + tq * 2;
                        float b0v = bias[col], b1v = bias[col + 1];
                        outu[row * 128 + (col >> 1)] =
                            pk(fmaxf(acc[mt][nt][0] + b0v, 0.f) * scale,
                               fmaxf(acc[mt][nt][1] + b1v, 0.f) * scale);
                        outu[(row + 8) * 128 + (col >> 1)] =
                            pk(fmaxf(acc[mt][nt][2] + b0v, 0.f) * scale,
                               fmaxf(acc[mt][nt][3] + b1v, 0.f) * scale);
                    }
                }
            }
        }
    }
}

// ============================================================
// Kernel D: fused flash attention (R6 structure; exp -> ex2, scores
// pre-scaled by log2e in Q). bf16, ldmatrix, double-buffered K/V.
// ============================================================
#define QSU (128 * 132)
#define KSU (64 * 132)
#define VSU (256 * 36)
#define OFF_K0 QSU
#define OFF_K1 (QSU + KSU)
#define OFF_V0 (QSU + 2 * KSU)
#define OFF_V1 (QSU + 2 * KSU + VSU)
#define FA_SMEM ((QSU + 2 * KSU + 2 * VSU) * 4)

__device__ __forceinline__ void stage_k(unsigned* dst, const unsigned* Ksrc, int kv0, int tid) {
#pragma unroll
    for (int i = 0; i < 8; i++) {
        int idx = i * 256 + tid;
        int r = idx >> 5, cu = (idx & 31) * 4;
        cpa16(&dst[r * 132 + cu], Ksrc + (kv0 + r) * 128 + cu);
    }
}
__device__ __forceinline__ void stage_v(unsigned* dst, const unsigned* Vsrc, int kv0, int tid) {
#pragma unroll
    for (int i = 0; i < 8; i++) {
        int idx = i * 256 + tid;
        int d = idx >> 3, cu = (idx & 7) * 4;
        cpa16(&dst[d * 36 + cu], Vsrc + d * 256 + (kv0 >> 1) + cu);
    }
}

__global__ __launch_bounds__(256) void k_attn(float* __restrict__ outp) {
    int bc = blockIdx.y;
    int q0 = blockIdx.x * 128;
    const unsigned* Qsrc = g_Qu + (size_t)bc * P_ * 128;
    const unsigned* Ksrc = g_Ku + (size_t)bc * P_ * 128;
    const unsigned* Vsrc = (const unsigned*)(g_Vt + (size_t)bc * D_ * P_);
    float* O = outp + (size_t)bc * P_ * D_;

    unsigned* Qs = sm_u;
    unsigned* Kb[2] = { sm_u + OFF_K0, sm_u + OFF_K1 };
    unsigned* Vb[2] = { sm_u + OFF_V0, sm_u + OFF_V1 };

    int tid = threadIdx.x;
    int wid = tid >> 5, lane = tid & 31;
    int g = lane >> 2, tq = lane & 3;
    int mr0 = wid * 16;

    unsigned q_lane = (unsigned)((mr0 + (lane & 7) + ((lane >> 3) & 1) * 8) * 132 + ((lane >> 4) & 1) * 4);
    unsigned k_lane = (unsigned)(((lane & 7) + ((lane >> 4) & 1) * 8) * 132 + ((lane >> 3) & 1) * 4);
    unsigned v_lane = (unsigned)(((lane & 7) + ((lane >> 4) & 1) * 8) * 36 + ((lane >> 3) & 1) * 4);

    // preload Q + tile 0
#pragma unroll
    for (int i = 0; i < 16; i++) {
        int idx = i * 256 + tid;
        int r = idx >> 5, cu = (idx & 31) * 4;
        cpa16(&Qs[r * 132 + cu], Qsrc + (q0 + r) * 128 + cu);
    }
    stage_k(Kb[0], Ksrc, 0, tid);
    stage_v(Vb[0], Vsrc, 0, tid);
    CP_COMMIT();

    float l0 = 0.f, l1 = 0.f;
    float Oa[32][4];
#pragma unroll
    for (int nt = 0; nt < 32; nt++)
#pragma unroll
        for (int e = 0; e < 4; e++) Oa[nt][e] = 0.f;

    CP_WAIT0();
    __syncthreads();

    unsigned qs_addr = (unsigned)__cvta_generic_to_shared(Qs) + q_lane * 4;

    for (int t = 0; t < 8; t++) {
        int cur = t & 1, nxt = cur ^ 1;
        if (t < 7) {
            stage_k(Kb[nxt], Ksrc, (t + 1) * 64, tid);
            stage_v(Vb[nxt], Vsrc, (t + 1) * 64, tid);
            CP_COMMIT();
        }
        unsigned ks_addr = (unsigned)__cvta_generic_to_shared(Kb[cur]) + k_lane * 4;
        unsigned vs_addr = (unsigned)__cvta_generic_to_shared(Vb[cur]) + v_lane * 4;

        // ---- S = Q @ K_tile^T (scores already x log2e) ----
        float sacc[8][4];
#pragma unroll
        for (int nt = 0; nt < 8; nt++)
#pragma unroll
            for (int e = 0; e < 4; e++) sacc[nt][e] = 0.f;

#pragma unroll
        for (int kg = 0; kg < 16; kg++) {
            unsigned a[4];
            ldsm4(a[0], a[1], a[2], a[3], qs_addr + kg * 32);
#pragma unroll
            for (int ntp = 0; ntp < 4; ntp++) {
                unsigned b0, b1, b2, b3;
                ldsm4(b0, b1, b2, b3, ks_addr + (ntp * 16 * 132 + kg * 8) * 4);
                unsigned bl[2] = { b0, b1 }, bh[2] = { b2, b3 };
                mma16(sacc[2 * ntp], a, bl);
                mma16(sacc[2 * ntp + 1], a, bh);
            }
        }

        // ---- exp via ex2 (softmax shift-invariant; scores bounded) ----
#pragma unroll
        for (int nt = 0; nt < 8; nt++) {
            sacc[nt][0] = ex2(sacc[nt][0]);
            sacc[nt][1] = ex2(sacc[nt][1]);
            sacc[nt][2] = ex2(sacc[nt][2]);
            sacc[nt][3] = ex2(sacc[nt][3]);
            l0 += sacc[nt][0] + sacc[nt][1];
            l1 += sacc[nt][2] + sacc[nt][3];
        }

        // ---- O += P @ V_tile ----
#pragma unroll
        for (int kg = 0; kg < 4; kg++) {
            unsigned a[4];
            a[0] = pk(sacc[2 * kg][0], sacc[2 * kg][1]);
            a[1] = pk(sacc[2 * kg][2], sacc[2 * kg][3]);
            a[2] = pk(sacc[2 * kg + 1][0], sacc[2 * kg + 1][1]);
            a[3] = pk(sacc[2 * kg + 1][2], sacc[2 * kg + 1][3]);
#pragma unroll
            for (int ntp = 0; ntp < 16; ntp++) {
                unsigned b0, b1, b2, b3;
                ldsm4(b0, b1, b2, b3, vs_addr + (ntp * 16 * 36 + kg * 8) * 4);
                unsigned bl[2] = { b0, b1 }, bh[2] = { b2, b3 };
                mma16(Oa[2 * ntp], a, bl);
                mma16(Oa[2 * ntp + 1], a, bh);
            }
        }

        CP_WAIT0();
        __syncthreads();
    }

    // ---- epilogue: deferred l reduction (quad lanes share rows) ----
#pragma unroll
    for (int o = 1; o <= 2; o <<= 1) {
        l0 += __shfl_xor_sync(0xFFFFFFFFu, l0, o);
        l1 += __shfl_xor_sync(0xFFFFFFFFu, l1, o);
    }
    float inv0 = 1.f / l0, inv1 = 1.f / l1;
    int row0 = q0 + mr0 + g;
#pragma unroll
    for (int nt = 0; nt < 32; nt++) {
        int col = nt * 8 + tq * 2;
        *(float2*)&O[row0 * D_ + col] = make_float2(Oa[nt][0] * inv0, Oa[nt][1] * inv0);
        *(float2*)&O[(row0 + 8) * D_ + col] = make_float2(Oa[nt][2] * inv1, Oa[nt][3] * inv1);
    }
}

// ============================================================
extern "C" void kernel_launch(void* const* d_in, const int* in_sizes, int n_in,
                              void* d_out, int out_size) {
    const float* query = (const float*)d_in[0];
    const float* aw    = (const float*)d_in[1];
    const float* wq    = (const float*)d_in[2];
    const float* wk    = (const float*)d_in[3];
    const float* wv    = (const float*)d_in[4];
    const float* bq    = (const float*)d_in[5];
    const float* bk    = (const float*)d_in[6];
    const float* bv    = (const float*)d_in[7];
    float* out = (float*)d_out;

    cudaFuncSetAttribute(k_attn, cudaFuncAttributeMaxDynamicSharedMemorySize, FA_SMEM);
    cudaFuncSetAttribute(k_proj, cudaFuncAttributeMaxDynamicSharedMemorySize, PJ_SMEM);

    k_prep<<<(B_ * P_ * D_ / 4) / 256, 256>>>(query, aw);
    k_wconv<<<3 * 16 * 4 * 8, 256>>>(wq, wk, wv);

    dim3 gp(P_ / 128, 1, B_ * C_ * 3);
    k_proj<<<gp, 256, PJ_SMEM>>>(bq, bk, bv);

    dim3 ga(P_ / 128, B_ * C_);
    k_attn<<<ga, 256, FA_SMEM>>>(out);
}

// round 15
// speedup vs baseline: 1.0562x; 1.0018x over previous
#include <cuda_runtime.h>
#include <cuda_bf16.h>
#include <cstdint>

#define B_ 16
#define C_ 16
#define P_ 512
#define D_ 256

// ---- scratch (__device__ globals) ----
__device__ unsigned g_Qb[(size_t)B_ * C_ * P_ * 128];   // bf16 query pairs [bc][p][kpair]
__device__ unsigned g_Cx[(size_t)B_ * C_ * P_ * 128];   // bf16 ctx pairs   [bc][p][kpair]
__device__ unsigned g_Wb[(size_t)3 * C_ * D_ * 128];    // bf16 W pairs [which][c][n][kpair]
__device__ unsigned g_Qu[(size_t)B_ * C_ * P_ * 128];   // Q proj out [p][kpair] (scaled by log2e/16)
__device__ unsigned g_Ku[(size_t)B_ * C_ * P_ * 128];   // K proj out [p][kpair]
__device__ __nv_bfloat16 g_Vt[(size_t)B_ * C_ * D_ * P_]; // V proj out, transposed [d][p]

__device__ __forceinline__ unsigned pk(float lo, float hi) {
    unsigned r;
    asm("cvt.rn.bf16x2.f32 %0, %1, %2;" : "=r"(r) : "f"(hi), "f"(lo));
    return r;
}
__device__ __forceinline__ float ex2(float x) {
    float y;
    asm("ex2.approx.f32 %0, %1;" : "=f"(y) : "f"(x));
    return y;
}
__device__ __forceinline__ void mma16(float* c, const unsigned* a, const unsigned* b) {
    asm volatile(
        "mma.sync.aligned.m16n8k16.row.col.f32.bf16.bf16.f32 "
        "{%0,%1,%2,%3}, {%4,%5,%6,%7}, {%8,%9}, {%0,%1,%2,%3};"
        : "+f"(c[0]), "+f"(c[1]), "+f"(c[2]), "+f"(c[3])
        : "r"(a[0]), "r"(a[1]), "r"(a[2]), "r"(a[3]), "r"(b[0]), "r"(b[1]));
}
__device__ __forceinline__ void ldsm4(unsigned& r0, unsigned& r1, unsigned& r2, unsigned& r3, unsigned addr) {
    asm volatile("ldmatrix.sync.aligned.m8n8.x4.shared.b16 {%0,%1,%2,%3}, [%4];"
        : "=r"(r0), "=r"(r1), "=r"(r2), "=r"(r3) : "r"(addr));
}
__device__ __forceinline__ void cpa16(void* s, const void* g) {
    unsigned sa = (unsigned)__cvta_generic_to_shared(s);
    asm volatile("cp.async.ca.shared.global [%0], [%1], 16;" :: "r"(sa), "l"(g));
}
#define CP_COMMIT() asm volatile("cp.async.commit_group;")
#define CP_WAIT0()  asm volatile("cp.async.wait_group 0;")
#define CP_WAIT1()  asm volatile("cp.async.wait_group 1;")

// ============================================================
// Kernel A: prep — bf16 query copy + bf16 ctx (= S - aw*q)
// ============================================================
__global__ __launch_bounds__(256) void k_prep(const float* __restrict__ query,
                                              const float* __restrict__ aw) {
    int idx = blockIdx.x * 256 + threadIdx.x;
    int d4 = idx & 63;
    int p  = (idx >> 6) & 511;
    int b  = idx >> 15;

    float4 qv[16];
    float4 S = make_float4(0.f, 0.f, 0.f, 0.f);
#pragma unroll
    for (int c = 0; c < 16; c++) {
        qv[c] = *(const float4*)(query + ((size_t)((b * 16 + c) * 512 + p) * 64 + d4) * 4);
        float4 a = *(const float4*)(aw + ((size_t)(c * 512 + p) * 64 + d4) * 4);
        S.x += a.x * qv[c].x; S.y += a.y * qv[c].y;
        S.z += a.z * qv[c].z; S.w += a.w * qv[c].w;
        uint2 u; u.x = pk(qv[c].x, qv[c].y); u.y = pk(qv[c].z, qv[c].w);
        *(uint2*)&g_Qb[(size_t)((b * 16 + c) * 512 + p) * 128 + d4 * 2] = u;
    }
#pragma unroll
    for (int c = 0; c < 16; c++) {
        float4 a = *(const float4*)(aw + ((size_t)(c * 512 + p) * 64 + d4) * 4);
        float4 cx;
        cx.x = fmaf(-a.x, qv[c].x, S.x);
        cx.y = fmaf(-a.y, qv[c].y, S.y);
        cx.z = fmaf(-a.z, qv[c].z, S.z);
        cx.w = fmaf(-a.w, qv[c].w, S.w);
        uint2 u; u.x = pk(cx.x, cx.y); u.y = pk(cx.z, cx.w);
        *(uint2*)&g_Cx[(size_t)((b * 16 + c) * 512 + p) * 128 + d4 * 2] = u;
    }
}

// ============================================================
// Kernel B: weight convert+transpose -> g_Wb[which][c][n][kpair]
// ============================================================
__global__ __launch_bounds__(256) void k_wconv(const float* __restrict__ wq,
                                               const float* __restrict__ wk,
                                               const float* __restrict__ wv) {
    __shared__ unsigned sm[32][33];
    int t = blockIdx.x;
    int nb = t & 7, kb = (t >> 3) & 3, c = (t >> 5) & 15, w = t >> 9;
    const float* W = ((w == 0) ? wq : (w == 1) ? wk : wv) + c * D_ * D_;
    int tid = threadIdx.x;
    int coln = tid & 31, rowk = tid >> 5;
#pragma unroll
    for (int i = 0; i < 4; i++) {
        int kk = kb * 32 + rowk + i * 8;
        int n = nb * 32 + coln;
        sm[rowk + i * 8][coln] = pk(W[(2 * kk) * D_ + n], W[(2 * kk + 1) * D_ + n]);
    }
    __syncthreads();
    unsigned* outb = g_Wb + (size_t)(w * 16 + c) * D_ * 128;
    int kkc = tid & 31, rn = tid >> 5;
#pragma unroll
    for (int i = 0; i < 4; i++) {
        int n = nb * 32 + rn + i * 8;
        outb[n * 128 + kb * 32 + kkc] = sm[kkc][rn + i * 8];
    }
}

// ============================================================
// Kernel C: projections v5 (R14 measured-best) — A tile resident,
// persistent over both n-blocks, 3-stage W pipeline, 1 sync/step,
// reg-capped 2 CTAs/SM.
// ============================================================
#define PA_WORDS (128 * 132)
#define PW_STG   (128 * 20)
#define PJ_SMEM  ((PA_WORDS + 3 * PW_STG) * 4)

extern __shared__ unsigned sm_u[];

__global__ __launch_bounds__(256, 2) void k_proj(
    const float* __restrict__ bq, const float* __restrict__ bk, const float* __restrict__ bv)
{
    int z = blockIdx.z;
    int which = z % 3;
    int bc = z / 3;
    int c = bc & 15;

    const float* bias = ((which == 0) ? bq : (which == 1) ? bk : bv) + c * D_;
    const unsigned* Asrc = ((which == 0) ? g_Qb : g_Cx) + (size_t)bc * P_ * 128;
    const unsigned* Bsrc = g_Wb + (size_t)(which * 16 + c) * D_ * 128;

    int m0 = blockIdx.x * 128;

    int tid = threadIdx.x;
    int wid = tid >> 5, lane = tid & 31;
    int wm = wid & 1, wn = wid >> 1;
    int g = lane >> 2, tq = lane & 3;

    unsigned a_lane = (unsigned)((wm * 64 + (lane & 7) + ((lane >> 3) & 1) * 8) * 132 + ((lane >> 4) & 1) * 4);
    unsigned b_lane = (unsigned)((wn * 32 + (lane & 7) + ((lane >> 4) & 1) * 8) * 20 + ((lane >> 3) & 1) * 4);

    unsigned* smA = sm_u;
    unsigned* smW = sm_u + PA_WORDS;

#pragma unroll
    for (int i = 0; i < 16; i++) {
        int idx = i * 256 + tid;
        int r = idx >> 5, cu = (idx & 31) * 4;
        cpa16(&smA[r * 132 + cu], Asrc + (m0 + r) * 128 + cu);
    }
    CP_COMMIT();

    auto stageW = [&](int s) {
        unsigned* Ws = smW + (s % 3) * PW_STG;
        int nb = s >> 3, kp = (s & 7) * 16;
#pragma unroll
        for (int i = 0; i < 2; i++) {
            int idx = tid + i * 256;
            int r = idx >> 2, c4 = (idx & 3) * 4;
            cpa16(&Ws[r * 20 + c4], Bsrc + (nb * 128 + r) * 128 + kp + c4);
        }
        CP_COMMIT();
    };

    stageW(0);
    stageW(1);

    unsigned as_base = (unsigned)__cvta_generic_to_shared(smA) + a_lane * 4;

    float acc[4][4][4];

    for (int s = 0; s < 16; s++) {
        if ((s & 7) == 0) {
#pragma unroll
            for (int i = 0; i < 4; i++)
#pragma unroll
                for (int j = 0; j < 4; j++)
#pragma unroll
                    for (int e = 0; e < 4; e++) acc[i][j][e] = 0.f;
        }

        if (s < 15) { CP_WAIT1(); } else { CP_WAIT0(); }
        __syncthreads();
        if (s < 14) stageW(s + 2);

        unsigned* Ws = smW + (s % 3) * PW_STG;
        unsigned bs_addr = (unsigned)__cvta_generic_to_shared(Ws) + b_lane * 4;
        unsigned kbase = (unsigned)((s & 7) * 16);
#pragma unroll
        for (int kg = 0; kg < 2; kg++) {
            unsigned a[4][4];
#pragma unroll
            for (int mt = 0; mt < 4; mt++)
                ldsm4(a[mt][0], a[mt][1], a[mt][2], a[mt][3],
                      as_base + (mt * 16 * 132 + kbase + kg * 8) * 4);
#pragma unroll
            for (int ntp = 0; ntp < 2; ntp++) {
                unsigned b0, b1, b2, b3;
                ldsm4(b0, b1, b2, b3, bs_addr + (ntp * 16 * 20 + kg * 8) * 4);
                unsigned bl[2] = { b0, b1 }, bh[2] = { b2, b3 };
#pragma unroll
                for (int mt = 0; mt < 4; mt++) {
                    mma16(acc[mt][2 * ntp], a[mt], bl);
                    mma16(acc[mt][2 * ntp + 1], a[mt], bh);
                }
            }
        }

        if ((s & 7) == 7) {
            int n0 = (s >> 3) * 128;
            if (which == 2) {
                __nv_bfloat16* vt = g_Vt + (size_t)bc * D_ * P_;
#pragma unroll
                for (int mt = 0; mt < 4; mt++) {
#pragma unroll
                    for (int nt = 0; nt < 4; nt++) {
                        int row = m0 + wm * 64 + mt * 16 + g;
                        int col = n0 + wn * 32 + nt * 8 + tq * 2;
                        float b0v = bias[col], b1v = bias[col + 1];
                        vt[col * P_ + row]           = __float2bfloat16(fmaxf(acc[mt][nt][0] + b0v, 0.f));
                        vt[(col + 1) * P_ + row]     = __float2bfloat16(fmaxf(acc[mt][nt][1] + b1v, 0.f));
                        vt[col * P_ + row + 8]       = __float2bfloat16(fmaxf(acc[mt][nt][2] + b0v, 0.f));
                        vt[(col + 1) * P_ + row + 8] = __float2bfloat16(fmaxf(acc[mt][nt][3] + b1v, 0.f));
                    }
                }
            } else {
                unsigned* outu = ((which == 0) ? g_Qu : g_Ku) + (size_t)bc * P_ * 128;
                float scale = (which == 0) ? 0.09016994f : 1.f;  // (1/16)*log2(e)
#pragma unroll
                for (int mt = 0; mt < 4; mt++) {
#pragma unroll
                    for (int nt = 0; nt < 4; nt++) {
                        int row = m0 + wm * 64 + mt * 16 + g;
                        int col = n0 + wn * 32 + nt * 8 + tq * 2;
                        float b0v = bias[col], b1v = bias[col + 1];
                        outu[row * 128 + (col >> 1)] =
                            pk(fmaxf(acc[mt][nt][0] + b0v, 0.f) * scale,
                               fmaxf(acc[mt][nt][1] + b1v, 0.f) * scale);
                        outu[(row + 8) * 128 + (col >> 1)] =
                            pk(fmaxf(acc[mt][nt][2] + b0v, 0.f) * scale,
                               fmaxf(acc[mt][nt][3] + b1v, 0.f) * scale);
                    }
                }
            }
        }
    }
}

// ============================================================
// Kernel D v5: flash attention — column-pair software pipeline.
// Per tile: S(pair p+1) issued BETWEEN exp(pair p) and O(pair p)
// so MUFU exp retires under tensor work. bf16, ldmatrix, dbl-buffered.
// ============================================================
#define QSU (128 * 132)
#define KSU (64 * 132)
#define VSU (256 * 36)
#define OFF_K0 QSU
#define OFF_K1 (QSU + KSU)
#define OFF_V0 (QSU + 2 * KSU)
#define OFF_V1 (QSU + 2 * KSU + VSU)
#define FA_SMEM ((QSU + 2 * KSU + 2 * VSU) * 4)

__device__ __forceinline__ void stage_k(unsigned* dst, const unsigned* Ksrc, int kv0, int tid) {
#pragma unroll
    for (int i = 0; i < 8; i++) {
        int idx = i * 256 + tid;
        int r = idx >> 5, cu = (idx & 31) * 4;
        cpa16(&dst[r * 132 + cu], Ksrc + (kv0 + r) * 128 + cu);
    }
}
__device__ __forceinline__ void stage_v(unsigned* dst, const unsigned* Vsrc, int kv0, int tid) {
#pragma unroll
    for (int i = 0; i < 8; i++) {
        int idx = i * 256 + tid;
        int d = idx >> 3, cu = (idx & 7) * 4;
        cpa16(&dst[d * 36 + cu], Vsrc + d * 256 + (kv0 >> 1) + cu);
    }
}

// S-GEMM for one column pair (16 kv cols): 16 k-groups, 2 MMAs each.
__device__ __forceinline__ void s_pair(float* s, unsigned qs_addr, unsigned ks_addr, int p) {
#pragma unroll
    for (int e = 0; e < 8; e++) s[e] = 0.f;
#pragma unroll
    for (int kg = 0; kg < 16; kg++) {
        unsigned a[4];
        ldsm4(a[0], a[1], a[2], a[3], qs_addr + kg * 32);
        unsigned b0, b1, b2, b3;
        ldsm4(b0, b1, b2, b3, ks_addr + (p * 16 * 132 + kg * 8) * 4);
        unsigned bl[2] = { b0, b1 }, bh[2] = { b2, b3 };
        mma16(s, a, bl);
        mma16(s + 4, a, bh);
    }
}

__global__ __launch_bounds__(256) void k_attn(float* __restrict__ outp) {
    int bc = blockIdx.y;
    int q0 = blockIdx.x * 128;
    const unsigned* Qsrc = g_Qu + (size_t)bc * P_ * 128;
    const unsigned* Ksrc = g_Ku + (size_t)bc * P_ * 128;
    const unsigned* Vsrc = (const unsigned*)(g_Vt + (size_t)bc * D_ * P_);
    float* O = outp + (size_t)bc * P_ * D_;

    unsigned* Qs = sm_u;
    unsigned* Kb[2] = { sm_u + OFF_K0, sm_u + OFF_K1 };
    unsigned* Vb[2] = { sm_u + OFF_V0, sm_u + OFF_V1 };

    int tid = threadIdx.x;
    int wid = tid >> 5, lane = tid & 31;
    int g = lane >> 2, tq = lane & 3;
    int mr0 = wid * 16;

    unsigned q_lane = (unsigned)((mr0 + (lane & 7) + ((lane >> 3) & 1) * 8) * 132 + ((lane >> 4) & 1) * 4);
    unsigned k_lane = (unsigned)(((lane & 7) + ((lane >> 4) & 1) * 8) * 132 + ((lane >> 3) & 1) * 4);
    unsigned v_lane = (unsigned)(((lane & 7) + ((lane >> 4) & 1) * 8) * 36 + ((lane >> 3) & 1) * 4);

    // preload Q + tile 0
#pragma unroll
    for (int i = 0; i < 16; i++) {
        int idx = i * 256 + tid;
        int r = idx >> 5, cu = (idx & 31) * 4;
        cpa16(&Qs[r * 132 + cu], Qsrc + (q0 + r) * 128 + cu);
    }
    stage_k(Kb[0], Ksrc, 0, tid);
    stage_v(Vb[0], Vsrc, 0, tid);
    CP_COMMIT();

    float l0 = 0.f, l1 = 0.f;
    float Oa[32][4];
#pragma unroll
    for (int nt = 0; nt < 32; nt++)
#pragma unroll
        for (int e = 0; e < 4; e++) Oa[nt][e] = 0.f;

    CP_WAIT0();
    __syncthreads();

    unsigned qs_addr = (unsigned)__cvta_generic_to_shared(Qs) + q_lane * 4;

    for (int t = 0; t < 8; t++) {
        int cur = t & 1, nxt = cur ^ 1;
        if (t < 7) {
            stage_k(Kb[nxt], Ksrc, (t + 1) * 64, tid);
            stage_v(Vb[nxt], Vsrc, (t + 1) * 64, tid);
            CP_COMMIT();
        }
        unsigned ks_addr = (unsigned)__cvta_generic_to_shared(Kb[cur]) + k_lane * 4;
        unsigned vs_addr = (unsigned)__cvta_generic_to_shared(Vb[cur]) + v_lane * 4;

        float sa[2][8];
        s_pair(sa[0], qs_addr, ks_addr, 0);

#pragma unroll
        for (int p = 0; p < 4; p++) {
            int cb = p & 1, nb = cb ^ 1;
            float* s = sa[cb];

            // exp of pair p (MUFU; retires under S(p+1) tensor work)
            s[0] = ex2(s[0]); s[1] = ex2(s[1]); s[2] = ex2(s[2]); s[3] = ex2(s[3]);
            s[4] = ex2(s[4]); s[5] = ex2(s[5]); s[6] = ex2(s[6]); s[7] = ex2(s[7]);

            // S-GEMM for next pair — independent of the exps above
            if (p < 3) s_pair(sa[nb], qs_addr, ks_addr, p + 1);

            // l accumulation (e0,e1 -> row g; e2,e3 -> row g+8)
            l0 += s[0] + s[1] + s[4] + s[5];
            l1 += s[2] + s[3] + s[6] + s[7];

            // pack + O-GEMM for pair p (V kv-slice kg = p)
            unsigned a[4];
            a[0] = pk(s[0], s[1]);
            a[1] = pk(s[2], s[3]);
            a[2] = pk(s[4], s[5]);
            a[3] = pk(s[6], s[7]);
#pragma unroll
            for (int ntp = 0; ntp < 16; ntp++) {
                unsigned b0, b1, b2, b3;
                ldsm4(b0, b1, b2, b3, vs_addr + (ntp * 16 * 36 + p * 8) * 4);
                unsigned bl[2] = { b0, b1 }, bh[2] = { b2, b3 };
                mma16(Oa[2 * ntp], a, bl);
                mma16(Oa[2 * ntp + 1], a, bh);
            }
        }

        CP_WAIT0();
        __syncthreads();
    }

    // ---- epilogue: deferred l reduction (quad lanes share rows) ----
#pragma unroll
    for (int o = 1; o <= 2; o <<= 1) {
        l0 += __shfl_xor_sync(0xFFFFFFFFu, l0, o);
        l1 += __shfl_xor_sync(0xFFFFFFFFu, l1, o);
    }
    float inv0 = 1.f / l0, inv1 = 1.f / l1;
    int row0 = q0 + mr0 + g;
#pragma unroll
    for (int nt = 0; nt < 32; nt++) {
        int col = nt * 8 + tq * 2;
        *(float2*)&O[row0 * D_ + col] = make_float2(Oa[nt][0] * inv0, Oa[nt][1] * inv0);
        *(float2*)&O[(row0 + 8) * D_ + col] = make_float2(Oa[nt][2] * inv1, Oa[nt][3] * inv1);
    }
}

// ============================================================
extern "C" void kernel_launch(void* const* d_in, const int* in_sizes, int n_in,
                              void* d_out, int out_size) {
    const float* query = (const float*)d_in[0];
    const float* aw    = (const float*)d_in[1];
    const float* wq    = (const float*)d_in[2];
    const float* wk    = (const float*)d_in[3];
    const float* wv    = (const float*)d_in[4];
    const float* bq    = (const float*)d_in[5];
    const float* bk    = (const float*)d_in[6];
    const float* bv    = (const float*)d_in[7];
    float* out = (float*)d_out;

    cudaFuncSetAttribute(k_attn, cudaFuncAttributeMaxDynamicSharedMemorySize, FA_SMEM);
    cudaFuncSetAttribute(k_proj, cudaFuncAttributeMaxDynamicSharedMemorySize, PJ_SMEM);

    k_prep<<<(B_ * P_ * D_ / 4) / 256, 256>>>(query, aw);
    k_wconv<<<3 * 16 * 4 * 8, 256>>>(wq, wk, wv);

    dim3 gp(P_ / 128, 1, B_ * C_ * 3);
    k_proj<<<gp, 256, PJ_SMEM>>>(bq, bk, bv);

    dim3 ga(P_ / 128, B_ * C_);
    k_attn<<<ga, 256, FA_SMEM>>>(out);
}